// round 4
// baseline (speedup 1.0000x reference)
#include <cuda_runtime.h>

// Problem constants (fixed by the dataset)
#define NN       262144           // nodes per tree (2^18)
#define NT       12               // B*C trees
#define HWPX     1048576          // H*W (2^20)
#define TOTAL    (NT * NN)
#define NN_SENT  262144           // root sentinel parent value

// ---------------------------------------------------------------------------
// Per-tree block-role layout (128-thread blocks), bid-order = pipeline order:
//   A  : contrib, 16 nodes/thread  -> 128 blocks/tree (block j: nodes [j*2048,(j+1)*2048))
//   C0 : walk-to-root  [0,2048)    -> 16 blocks
//   C1 : cascade [2048,32768)      -> 120 blocks (ILP2)
//   C2 : cascade [32768,131072)    -> 192 blocks (ILP4)
//   C3 : cascade [131072,262144)   -> 256 blocks (ILP4)
//   D  : pixel gather, 16 px/thr   -> 512 blocks
// AC = 712 blocks/tree, D = 512 blocks/tree.
// Global schedule: phase 0 = AC(t0); phases 1..11 = interleave{D(t-1), AC(t)};
// phase 12 = D(t11). Gather(t-1) co-resides with compute(t) -> resource overlap.
// ---------------------------------------------------------------------------
#define AC_BLKS   712
#define D_BLKS    512
#define PH_BLKS   (AC_BLKS + D_BLKS)   // 1224
#define GRID_BLKS (AC_BLKS + 11 * PH_BLKS + D_BLKS)  // 14688

// Scratch (allocation-free rule: __device__ globals)
__device__ float4 g_node[TOTAL];   // {c0,c1,c2,parent-as-float-bits}
__device__ float4 g_F[TOTAL];      // final {f0,f1,f2,_}
// Per-tree sync counters: 0:A2k 1:A32k 2:A128k 3:Aall 4:C0 5:C1 6:C2 7:C3 8:Ddone
__device__ int    g_sync[NT][16];  // zero-initialized; reset by last D block

__device__ __forceinline__ float sigmoidf_(float x) {
    return 1.0f / (1.0f + expf(-x));
}

__device__ __forceinline__ void block_wait(int* ctr, int target) {
    if (threadIdx.x == 0) {
        for (;;) {
            int v;
            asm volatile("ld.global.acquire.gpu.b32 %0, [%1];" : "=r"(v) : "l"(ctr));
            if (v >= target) break;
            __nanosleep(128);
        }
    }
    __syncthreads();
}

// call AFTER __syncthreads(); thread 0 only
__device__ __forceinline__ int ctr_inc(int* ctr) {
    return atomicAdd(ctr, 1);
}

// ---------------------------------------------------------------------------
// Role bodies
// ---------------------------------------------------------------------------
__device__ void role_contrib(int tree, int j,
                             const float4* __restrict__ attrs4,
                             const float4* __restrict__ residue4,
                             const int4*  __restrict__ parent4,
                             float w0, float w10, float w11, float w2,
                             float B0, float B1, float B2) {
    const int tid = threadIdx.x;
    const size_t quadBase = (size_t)tree * (NN / 4) + (size_t)j * 512;
#pragma unroll
    for (int k = 0; k < 4; k++) {
        size_t q = quadBase + k * 128 + tid;
        float4 A0 = __ldcs(&attrs4[3 * q + 0]);
        float4 A1 = __ldcs(&attrs4[3 * q + 1]);
        float4 A2 = __ldcs(&attrs4[3 * q + 2]);
        float4 R  = __ldcs(&residue4[q]);
        int4   P  = __ldcs(&parent4[q]);

        float a0[4] = {A0.x, A0.w, A1.z, A2.y};
        float a1[4] = {A0.y, A1.x, A1.w, A2.z};
        float a2[4] = {A0.z, A1.y, A2.x, A2.w};
        float r[4]  = {R.x, R.y, R.z, R.w};
        int   p[4]  = {P.x, P.y, P.z, P.w};

        float4* outp = g_node + 4 * q;
#pragma unroll
        for (int m = 0; m < 4; m++) {
            float c0 = sigmoidf_(fmaf(a0[m], w0, B0)) * r[m];
            float c1 = sigmoidf_(fmaf(a2[m], w11, fmaf(a1[m], w10, B1))) * r[m];
            float c2 = sigmoidf_(fmaf(a1[m], w2, B2)) * r[m];
            outp[m] = make_float4(c0, c1, c2, __int_as_float(p[m]));
        }
    }
    __syncthreads();
    if (threadIdx.x == 0) {
        __threadfence();
        int* S = g_sync[tree];
        ctr_inc(&S[3]);                 // Aall
        if (j < 64) ctr_inc(&S[2]);     // A128k  (covers [0,131072))
        if (j < 16) ctr_inc(&S[1]);     // A32k   (covers [0,32768))
        if (j < 1)  ctr_inc(&S[0]);     // A2k    (covers [0,2048))
    }
}

// walk-to-root for nodes [0,2048): parents of these nodes are < n (or sentinel)
__device__ void role_c0(int tree, int idx0) {
    int* S = g_sync[tree];
    block_wait(&S[0], 1);

    const int n = idx0 * 128 + threadIdx.x;          // [0,2048)
    const float4* nb = g_node + (size_t)tree * NN;

    float4 v = nb[n];
    float ax = v.x, ay = v.y, az = v.z;
    int p = __float_as_int(v.w);
    while (p != NN_SENT) {
        float4 u = __ldg(&nb[p]);
        ax += u.x; ay += u.y; az += u.z;
        p = __float_as_int(u.w);
    }
    g_F[(size_t)tree * NN + n] = make_float4(ax, ay, az, 0.0f);

    __syncthreads();
    if (threadIdx.x == 0) { __threadfence(); ctr_inc(&S[4]); }
}

// generic cascade: L independent chains per thread, lockstep advance
template <int L>
__device__ void role_cascade(int tree, int idx, int start, int span) {
    const float4* nb = g_node + (size_t)tree * NN;
    float4*       Fb = g_F    + (size_t)tree * NN;

    int   n[L], p[L];
    float ax[L], ay[L], az[L];
#pragma unroll
    for (int l = 0; l < L; l++) {
        n[l] = start + idx + l * span;
        float4 v = __ldg(&nb[n[l]]);
        ax[l] = v.x; ay[l] = v.y; az[l] = v.z;
        p[l] = __float_as_int(v.w);
    }
    bool any = true;
    while (any) {
        any = false;
        float4 u[L]; bool act[L];
#pragma unroll
        for (int l = 0; l < L; l++) {
            act[l] = (p[l] >= start);
            if (act[l]) u[l] = __ldg(&nb[p[l]]);
        }
#pragma unroll
        for (int l = 0; l < L; l++) {
            if (act[l]) {
                ax[l] += u[l].x; ay[l] += u[l].y; az[l] += u[l].z;
                p[l] = __float_as_int(u[l].w);
                any = any || (p[l] >= start);
            }
        }
    }
#pragma unroll
    for (int l = 0; l < L; l++) {
        float4 f = __ldg(&Fb[p[l]]);
        Fb[n[l]] = make_float4(ax[l] + f.x, ay[l] + f.y, az[l] + f.z, 0.0f);
    }
}

__device__ void role_gather(int tree, int d_idx,
                            const int4* __restrict__ pix4,
                            float* __restrict__ out) {
    int* S = g_sync[tree];
    block_wait(&S[7], 256);   // C3 done => all F final (transitive)

    const int tid = threadIdx.x;
    const float4* Fb = g_F + (size_t)tree * NN;
    float* obase = out + (size_t)tree * 3 * HWPX;

#pragma unroll
    for (int k = 0; k < 4; k++) {
        int lq = d_idx * 512 + k * 128 + tid;                // quad index within tree
        int4 nd = __ldcs(&pix4[(size_t)tree * (HWPX / 4) + lq]);

        float4 F0 = __ldg(&Fb[nd.x]);
        float4 F1 = __ldg(&Fb[nd.y]);
        float4 F2 = __ldg(&Fb[nd.z]);
        float4 F3 = __ldg(&Fb[nd.w]);

        float* o = obase + 4 * (size_t)lq;
        __stcs((float4*)(o),            make_float4(F0.x, F1.x, F2.x, F3.x));
        __stcs((float4*)(o + HWPX),     make_float4(F0.y, F1.y, F2.y, F3.y));
        __stcs((float4*)(o + 2 * HWPX), make_float4(F0.z, F1.z, F2.z, F3.z));
    }

    __syncthreads();
    if (threadIdx.x == 0) {
        __threadfence();
        int old = ctr_inc(&S[8]);
        if (old == D_BLKS - 1) {
            // last gather block of this tree: reset counters for next replay
#pragma unroll
            for (int i = 0; i < 9; i++) S[i] = 0;
            __threadfence();
        }
    }
}

// ---------------------------------------------------------------------------
// Mega-kernel: decode bid -> (tree, role) per the interleaved phase schedule.
// ---------------------------------------------------------------------------
__global__ void __launch_bounds__(128)
k_mega(const float4* __restrict__ attrs4,
       const float4* __restrict__ residue4,
       const int4*  __restrict__ parent4,
       const int4*  __restrict__ pix4,
       float* __restrict__ out,
       const float* __restrict__ W0, const float* __restrict__ W1,
       const float* __restrict__ W2,
       const float* __restrict__ b0, const float* __restrict__ b1,
       const float* __restrict__ b2) {
    const int bid = blockIdx.x;

    int tree, ac_idx = -1, d_idx = -1;
    if (bid < AC_BLKS) {                         // phase 0: AC of tree 0
        tree = 0; ac_idx = bid;
    } else if (bid < AC_BLKS + 11 * PH_BLKS) {   // interleaved phases 1..11
        int s = bid - AC_BLKS;
        int phase = s / PH_BLKS;                 // 0..10
        int w = s - phase * PH_BLKS;             // slot within phase
        int nD  = (w * D_BLKS) / PH_BLKS;
        int nD1 = ((w + 1) * D_BLKS) / PH_BLKS;
        if (nD1 > nD) { tree = phase;     d_idx  = nD; }
        else          { tree = phase + 1; ac_idx = w - nD; }
    } else {                                     // tail: D of tree 11
        tree = 11; d_idx = bid - (AC_BLKS + 11 * PH_BLKS);
    }

    if (d_idx >= 0) {
        role_gather(tree, d_idx, pix4, out);
        return;
    }

    int* S = g_sync[tree];
    if (ac_idx < 128) {
        role_contrib(tree, ac_idx, attrs4, residue4, parent4,
                     __ldg(W0), __ldg(&W1[0]), __ldg(&W1[1]), __ldg(W2),
                     __ldg(b0), __ldg(b1), __ldg(b2));
    } else if (ac_idx < 144) {
        role_c0(tree, ac_idx - 128);
    } else if (ac_idx < 264) {
        block_wait(&S[1], 16);                   // A covers [0,32768)
        block_wait(&S[4], 16);                   // C0 done
        role_cascade<2>(tree, (ac_idx - 144) * 128 + threadIdx.x, 2048, 15360);
        __syncthreads();
        if (threadIdx.x == 0) { __threadfence(); ctr_inc(&S[5]); }
    } else if (ac_idx < 456) {
        block_wait(&S[2], 64);                   // A covers [0,131072)
        block_wait(&S[5], 120);                  // C1 done
        role_cascade<4>(tree, (ac_idx - 264) * 128 + threadIdx.x, 32768, 24576);
        __syncthreads();
        if (threadIdx.x == 0) { __threadfence(); ctr_inc(&S[6]); }
    } else {
        block_wait(&S[3], 128);                  // all A
        block_wait(&S[6], 192);                  // C2 done
        role_cascade<4>(tree, (ac_idx - 456) * 128 + threadIdx.x, 131072, 32768);
        __syncthreads();
        if (threadIdx.x == 0) { __threadfence(); ctr_inc(&S[7]); }
    }
}

// ---------------------------------------------------------------------------
// Entry point
// Inputs: attrs, residue, W0, W1, W2, b0, b1, b2, parent, pixel_node
// ---------------------------------------------------------------------------
extern "C" void kernel_launch(void* const* d_in, const int* in_sizes, int n_in,
                              void* d_out, int out_size) {
    const float* attrs   = (const float*)d_in[0];
    const float* residue = (const float*)d_in[1];
    const float* W0      = (const float*)d_in[2];
    const float* W1      = (const float*)d_in[3];
    const float* W2      = (const float*)d_in[4];
    const float* b0      = (const float*)d_in[5];
    const float* b1      = (const float*)d_in[6];
    const float* b2      = (const float*)d_in[7];
    const int*   parent  = (const int*)d_in[8];
    const int*   pix     = (const int*)d_in[9];
    float*       out     = (float*)d_out;

    k_mega<<<GRID_BLKS, 128>>>((const float4*)attrs, (const float4*)residue,
                               (const int4*)parent, (const int4*)pix, out,
                               W0, W1, W2, b0, b1, b2);
}